// round 9
// baseline (speedup 1.0000x reference)
#include <cuda_runtime.h>
#include <math.h>

// PINN forward + forward-mode JVPs (T, dT/dz, dT/dt, d2T/dz2)
// MLP: 3 -> 128 -> 128 -> 64 -> 1, tanh activations.
//
// R9: FFMA2 mainloop with FULLY-RESIDENT duplicated weights.
//  - TPB=256, PTS=32 (1 point/thread): A+B activations = 64KB, leaving
//    128KB smem for the COMPLETE {w,w}-duplicated W2. Staged ONCE before
//    layer 1 (accumulators dead) -- no mid-loop restage (R6 spill bug),
//    no per-k pack MOVs (R7 alu bloat).
//  - W3dup (64KB) restages into the same buffer after layer 2, again with
//    accumulators dead.
//  - __launch_bounds__(256,1): up to 255 regs/thread, no spill pressure.
//  - Layer-2 k-step: 32 FFMA2 + 2 LDS.64 + 8 uniform LDS.128 = 42 issue
//    slots vs 64 fma-pipe cycles -> pipe-bound with headroom.

#define TPB 256
#define PTS 32
#define H1  128
#define H2  128
#define H3  64

typedef unsigned long long ull;

__device__ __forceinline__ ull ffma2(ull a, ull b, ull c) {
    ull d;
    asm("fma.rn.f32x2 %0, %1, %2, %3;" : "=l"(d) : "l"(a), "l"(b), "l"(c));
    return d;
}
__device__ __forceinline__ ull pack2(float lo, float hi) {
    ull v;
    asm("mov.b64 %0, {%1, %2};" : "=l"(v) : "f"(lo), "f"(hi));
    return v;
}
__device__ __forceinline__ float2 unpack2(ull v) {
    float2 r;
    asm("mov.b64 {%0, %1}, %2;" : "=f"(r.x), "=f"(r.y) : "l"(v));
    return r;
}
// branch-free tanh: 1 - 2/(exp(2u)+1); exact limits at +-inf.
__device__ __forceinline__ float fast_tanh(float u) {
    float e, r;
    asm("ex2.approx.f32 %0, %1;" : "=f"(e) : "f"(u * 2.8853900817779268f));
    asm("rcp.approx.f32 %0, %1;" : "=f"(r) : "f"(e + 1.0f));
    return fmaf(-2.0f, r, 1.0f);
}
// tanh JVP epilogue on packed pairs.
__device__ __forceinline__ void tanh_jvp(ull u01, ull u23, ull* h01, ull* h23) {
    float2 v01 = unpack2(u01);   // x=u, y=u_dz
    float2 v23 = unpack2(u23);   // x=u_dt, y=u_dzz
    float h = fast_tanh(v01.x);
    float s = 1.0f - h * h;
    float hdz  = s * v01.y;
    float hdt  = s * v23.x;
    float hdzz = fmaf(-2.0f * h * hdz, v01.y, s * v23.y);
    *h01 = pack2(h, hdz);
    *h23 = pack2(hdt, hdzz);
}

__global__ __launch_bounds__(TPB, 1)
void pinn_fused_kernel(const float* __restrict__ x,
                       const float* __restrict__ W1, const float* __restrict__ b1,
                       const float* __restrict__ W2, const float* __restrict__ b2,
                       const float* __restrict__ W3, const float* __restrict__ b3,
                       const float* __restrict__ W4, const float* __restrict__ b4,
                       float* __restrict__ out)
{
    extern __shared__ float smem[];
    // A: {h,hdz}[128 units][32 pts] float2 = 32KB
    // B: {hdt,hdzz}[128][32] float2        = 32KB
    // Wdup: 16384 ull = 128KB (full W2dup; later W3dup in first 64KB)
    float2* A    = (float2*)smem;
    float2* B    = A + H1 * PTS;
    ull*    Wdup = (ull*)(B + H1 * PTS);

    const int tid  = threadIdx.x;
    const int lane = tid & 31;
    const int warp = tid >> 5;          // 0..7
    const int blk  = blockIdx.x;

    // -------- stage FULL W2dup (128KB), accumulators not yet live --------
    {
        const float4* src = (const float4*)W2;
        #pragma unroll
        for (int it = 0; it < (H1 * H2 / 4) / TPB; it++) {   // 16
            int i = tid + it * TPB;
            float4 w = __ldg(&src[i]);
            ulonglong2* d = (ulonglong2*)(Wdup + i * 4);
            d[0] = make_ulonglong2(pack2(w.x, w.x), pack2(w.y, w.y));
            d[1] = make_ulonglong2(pack2(w.z, w.z), pack2(w.w, w.w));
        }
    }

    // ---------------- Layer 1: 3 -> 128 (K=3 direct) ----------------
    {
        int pg = blk * PTS + lane;
        float x0 = x[pg * 3 + 0];
        float x1 = x[pg * 3 + 1];
        float x2 = x[pg * 3 + 2];
        #pragma unroll
        for (int it = 0; it < H1 / 8; it++) {
            int j = warp + it * 8;
            float w0 = __ldg(&W1[j]);
            float w1 = __ldg(&W1[H1 + j]);
            float w2 = __ldg(&W1[2 * H1 + j]);
            float u  = fmaf(x0, w0, fmaf(x1, w1, fmaf(x2, w2, __ldg(&b1[j]))));
            float h  = fast_tanh(u);
            float s  = 1.0f - h * h;
            float hdz  = s * w0;
            float hdt  = s * w1;
            float hdzz = -2.0f * h * hdz * w0;
            A[j * PTS + lane] = make_float2(h, hdz);
            B[j * PTS + lane] = make_float2(hdt, hdzz);
        }
    }
    __syncthreads();

    // ---------------- Layer 2: 128 -> 128 (in-place) ----------------
    // 8 warps x 16 cols; 1 point per thread (lane).
    {
        const int j0 = warp * 16;
        ull acc01[16], acc23[16];
        #pragma unroll
        for (int g = 0; g < 4; g++) {
            float4 bb = __ldg(&((const float4*)b2)[j0 / 4 + g]);
            acc01[g * 4 + 0] = pack2(bb.x, 0.0f);
            acc01[g * 4 + 1] = pack2(bb.y, 0.0f);
            acc01[g * 4 + 2] = pack2(bb.z, 0.0f);
            acc01[g * 4 + 3] = pack2(bb.w, 0.0f);
            acc23[g * 4 + 0] = 0ULL; acc23[g * 4 + 1] = 0ULL;
            acc23[g * 4 + 2] = 0ULL; acc23[g * 4 + 3] = 0ULL;
        }
        const ull* aA = (const ull*)A + lane;
        const ull* aB = (const ull*)B + lane;
        #pragma unroll 2
        for (int k = 0; k < H1; k++) {
            ull a01 = aA[k * PTS];
            ull a23 = aB[k * PTS];
            const ulonglong2* wr = (const ulonglong2*)(Wdup + k * H2 + j0);
            #pragma unroll
            for (int g = 0; g < 8; g++) {
                ulonglong2 w2v = wr[g];
                acc01[g * 2 + 0] = ffma2(a01, w2v.x, acc01[g * 2 + 0]);
                acc23[g * 2 + 0] = ffma2(a23, w2v.x, acc23[g * 2 + 0]);
                acc01[g * 2 + 1] = ffma2(a01, w2v.y, acc01[g * 2 + 1]);
                acc23[g * 2 + 1] = ffma2(a23, w2v.y, acc23[g * 2 + 1]);
            }
        }
        // epilogue in registers
        ull h01[16], h23[16];
        #pragma unroll
        for (int c = 0; c < 16; c++)
            tanh_jvp(acc01[c], acc23[c], &h01[c], &h23[c]);
        __syncthreads();   // all k-loop reads done (A/B and Wdup now dead)
        ull* oA = (ull*)A;
        ull* oB = (ull*)B;
        #pragma unroll
        for (int c = 0; c < 16; c++) {
            int j = j0 + c;
            oA[j * PTS + lane] = h01[c];
            oB[j * PTS + lane] = h23[c];
        }
        // -------- stage W3dup (64KB) into Wdup; accumulators dead --------
        const float4* src3 = (const float4*)W3;
        #pragma unroll
        for (int it = 0; it < (H2 * H3 / 4) / TPB; it++) {   // 8
            int i = tid + it * TPB;
            float4 w = __ldg(&src3[i]);
            ulonglong2* d = (ulonglong2*)(Wdup + i * 4);
            d[0] = make_ulonglong2(pack2(w.x, w.x), pack2(w.y, w.y));
            d[1] = make_ulonglong2(pack2(w.z, w.z), pack2(w.w, w.w));
        }
    }
    __syncthreads();

    // ---------------- Layer 3: 128 -> 64 (in-place) ----------------
    // 8 warps x 8 cols; 1 point per thread.
    {
        const int j0 = warp * 8;
        ull acc01[8], acc23[8];
        #pragma unroll
        for (int g = 0; g < 2; g++) {
            float4 bb = __ldg(&((const float4*)b3)[j0 / 4 + g]);
            acc01[g * 4 + 0] = pack2(bb.x, 0.0f);
            acc01[g * 4 + 1] = pack2(bb.y, 0.0f);
            acc01[g * 4 + 2] = pack2(bb.z, 0.0f);
            acc01[g * 4 + 3] = pack2(bb.w, 0.0f);
            acc23[g * 4 + 0] = 0ULL; acc23[g * 4 + 1] = 0ULL;
            acc23[g * 4 + 2] = 0ULL; acc23[g * 4 + 3] = 0ULL;
        }
        const ull* aA = (const ull*)A + lane;
        const ull* aB = (const ull*)B + lane;
        #pragma unroll 2
        for (int k = 0; k < H2; k++) {
            ull a01 = aA[k * PTS];
            ull a23 = aB[k * PTS];
            const ulonglong2* wr = (const ulonglong2*)(Wdup + k * H3 + j0);
            #pragma unroll
            for (int g = 0; g < 4; g++) {
                ulonglong2 w3v = wr[g];
                acc01[g * 2 + 0] = ffma2(a01, w3v.x, acc01[g * 2 + 0]);
                acc23[g * 2 + 0] = ffma2(a23, w3v.x, acc23[g * 2 + 0]);
                acc01[g * 2 + 1] = ffma2(a01, w3v.y, acc01[g * 2 + 1]);
                acc23[g * 2 + 1] = ffma2(a23, w3v.y, acc23[g * 2 + 1]);
            }
        }
        ull h01[8], h23[8];
        #pragma unroll
        for (int c = 0; c < 8; c++)
            tanh_jvp(acc01[c], acc23[c], &h01[c], &h23[c]);
        __syncthreads();   // all reads of layer-2 activations done
        ull* oA = (ull*)A;
        ull* oB = (ull*)B;
        #pragma unroll
        for (int c = 0; c < 8; c++) {
            int j = j0 + c;
            oA[j * PTS + lane] = h01[c];
            oB[j * PTS + lane] = h23[c];
        }
    }
    __syncthreads();

    // ---------------- Layer 4: 64 -> 1 (4 dots per point) ----------------
    if (tid < 128) {
        const int q = tid >> 5;            // quantity 0..3
        const int p = tid & 31;            // point
        const float2* hb = (q < 2 ? A : B);
        const bool hi = (q & 1);
        float dot = (q == 0) ? __ldg(&b4[0]) : 0.0f;
        #pragma unroll
        for (int k = 0; k < H3; k++) {
            float2 v = hb[k * PTS + p];
            dot = fmaf(hi ? v.y : v.x, __ldg(&W4[k]), dot);
        }
        out[(blk * PTS + p) * 4 + q] = dot;
    }
}

extern "C" void kernel_launch(void* const* d_in, const int* in_sizes, int n_in,
                              void* d_out, int out_size)
{
    const float* x  = (const float*)d_in[0];
    const float* W1 = (const float*)d_in[1];
    const float* b1 = (const float*)d_in[2];
    const float* W2 = (const float*)d_in[3];
    const float* b2 = (const float*)d_in[4];
    const float* W3 = (const float*)d_in[5];
    const float* b3 = (const float*)d_in[6];
    const float* W4 = (const float*)d_in[7];
    const float* b4 = (const float*)d_in[8];
    float* out = (float*)d_out;

    const int N = in_sizes[0] / 3;  // 262144
    // A(32KB) + B(32KB) + Wdup(128KB) = 192KB
    const int smem_bytes = (2 * H1 * PTS * 2 + H1 * H2 * 2) * (int)sizeof(float);

    cudaFuncSetAttribute(pinn_fused_kernel,
                         cudaFuncAttributeMaxDynamicSharedMemorySize, smem_bytes);

    pinn_fused_kernel<<<N / PTS, TPB, smem_bytes>>>(
        x, W1, b1, W2, b2, W3, b3, W4, b4, out);
}

// round 10
// speedup vs baseline: 1.0910x; 1.0910x over previous
#include <cuda_runtime.h>
#include <math.h>

// PINN forward + forward-mode JVPs (T, dT/dz, dT/dt, d2T/dz2)
// MLP: 3 -> 128 -> 128 -> 64 -> 1, tanh activations.
//
// R10: persistent FFMA2 kernel, all weights resident in smem.
//  - grid=148 (1 block/SM), TPB=512 (16 warps -> latency hiding that R9
//    lacked), each block loops over point-tiles of 32.
//  - Smem (224KB): A+B packed activations (64KB) + FULL {w,w}-duplicated
//    W2 (128KB) + scalar W3 (32KB). Staged ONCE per block for the whole
//    launch; no mid-loop restaging (R6 spill), no per-k W2 pack MOVs (R7).
//  - Layer 2: 16 warps x 8 cols, 1 pt/thread. Per k: 16 FFMA2 + 2 LDS.64
//    + 4 uniform LDS.128 = 22 issue slots vs 32 fma-pipe cycles.
//  - Layer 3 uses scalar W3 + 4 pack MOVs/k (only 1/3 of the work).
//  - Accumulators: 16 ull (L2) / 8 ull (L3) -> low reg pressure, no spills.

#define TPB   512
#define PTS   32
#define H1    128
#define H2    128
#define H3    64
#define NSM   148

typedef unsigned long long ull;

__device__ __forceinline__ ull ffma2(ull a, ull b, ull c) {
    ull d;
    asm("fma.rn.f32x2 %0, %1, %2, %3;" : "=l"(d) : "l"(a), "l"(b), "l"(c));
    return d;
}
__device__ __forceinline__ ull pack2(float lo, float hi) {
    ull v;
    asm("mov.b64 %0, {%1, %2};" : "=l"(v) : "f"(lo), "f"(hi));
    return v;
}
__device__ __forceinline__ float2 unpack2(ull v) {
    float2 r;
    asm("mov.b64 {%0, %1}, %2;" : "=f"(r.x), "=f"(r.y) : "l"(v));
    return r;
}
// branch-free tanh: 1 - 2/(exp(2u)+1); exact limits at +-inf.
__device__ __forceinline__ float fast_tanh(float u) {
    float e, r;
    asm("ex2.approx.f32 %0, %1;" : "=f"(e) : "f"(u * 2.8853900817779268f));
    asm("rcp.approx.f32 %0, %1;" : "=f"(r) : "f"(e + 1.0f));
    return fmaf(-2.0f, r, 1.0f);
}
// tanh JVP epilogue on packed pairs.
__device__ __forceinline__ void tanh_jvp(ull u01, ull u23, ull* h01, ull* h23) {
    float2 v01 = unpack2(u01);   // x=u, y=u_dz
    float2 v23 = unpack2(u23);   // x=u_dt, y=u_dzz
    float h = fast_tanh(v01.x);
    float s = 1.0f - h * h;
    float hdz  = s * v01.y;
    float hdt  = s * v23.x;
    float hdzz = fmaf(-2.0f * h * hdz, v01.y, s * v23.y);
    *h01 = pack2(h, hdz);
    *h23 = pack2(hdt, hdzz);
}

__global__ __launch_bounds__(TPB, 1)
void pinn_fused_kernel(const float* __restrict__ x,
                       const float* __restrict__ W1, const float* __restrict__ b1,
                       const float* __restrict__ W2, const float* __restrict__ b2,
                       const float* __restrict__ W3, const float* __restrict__ b3,
                       const float* __restrict__ W4, const float* __restrict__ b4,
                       float* __restrict__ out, int n_tiles)
{
    extern __shared__ float smem[];
    // A: {h,hdz}[128][32] float2 = 32KB ; B: {hdt,hdzz}[128][32] = 32KB
    // W2dup: 16384 ull = 128KB ; W3s: 8192 float = 32KB. Total 224KB.
    float2* A     = (float2*)smem;
    float2* B     = A + H1 * PTS;
    ull*    W2dup = (ull*)(B + H1 * PTS);
    float*  W3s   = (float*)(W2dup + H1 * H2);

    const int tid  = threadIdx.x;
    const int lane = tid & 31;
    const int warp = tid >> 5;          // 0..15

    // -------- stage all weights ONCE (no accumulators live) --------
    {
        const float4* src2 = (const float4*)W2;
        #pragma unroll
        for (int it = 0; it < (H1 * H2 / 4) / TPB; it++) {   // 8
            int i = tid + it * TPB;
            float4 w = __ldg(&src2[i]);
            ulonglong2* d = (ulonglong2*)(W2dup + i * 4);
            d[0] = make_ulonglong2(pack2(w.x, w.x), pack2(w.y, w.y));
            d[1] = make_ulonglong2(pack2(w.z, w.z), pack2(w.w, w.w));
        }
        const float4* src3 = (const float4*)W3;
        float4* d3 = (float4*)W3s;
        #pragma unroll
        for (int it = 0; it < (H2 * H3 / 4) / TPB; it++)     // 4
            d3[tid + it * TPB] = __ldg(&src3[tid + it * TPB]);
    }
    __syncthreads();

    // ================= persistent loop over point-tiles =================
    for (int tile = blockIdx.x; tile < n_tiles; tile += NSM) {

        // ---------------- Layer 1: 3 -> 128 (K=3 direct) ----------------
        {
            int pg = tile * PTS + lane;
            float x0 = x[pg * 3 + 0];
            float x1 = x[pg * 3 + 1];
            float x2 = x[pg * 3 + 2];
            #pragma unroll
            for (int it = 0; it < H1 / 16; it++) {           // 8
                int j = warp + it * 16;
                float w0 = __ldg(&W1[j]);
                float w1 = __ldg(&W1[H1 + j]);
                float w2 = __ldg(&W1[2 * H1 + j]);
                float u  = fmaf(x0, w0, fmaf(x1, w1, fmaf(x2, w2, __ldg(&b1[j]))));
                float h  = fast_tanh(u);
                float s  = 1.0f - h * h;
                float hdz  = s * w0;
                float hdt  = s * w1;
                float hdzz = -2.0f * h * hdz * w0;
                A[j * PTS + lane] = make_float2(h, hdz);
                B[j * PTS + lane] = make_float2(hdt, hdzz);
            }
        }
        __syncthreads();

        // ---------------- Layer 2: 128 -> 128 (in-place) ----------------
        // 16 warps x 8 cols; 1 point per thread (lane).
        {
            const int j0 = warp * 8;
            ull acc01[8], acc23[8];
            #pragma unroll
            for (int g = 0; g < 2; g++) {
                float4 bb = __ldg(&((const float4*)b2)[j0 / 4 + g]);
                acc01[g * 4 + 0] = pack2(bb.x, 0.0f);
                acc01[g * 4 + 1] = pack2(bb.y, 0.0f);
                acc01[g * 4 + 2] = pack2(bb.z, 0.0f);
                acc01[g * 4 + 3] = pack2(bb.w, 0.0f);
                acc23[g * 4 + 0] = 0ULL; acc23[g * 4 + 1] = 0ULL;
                acc23[g * 4 + 2] = 0ULL; acc23[g * 4 + 3] = 0ULL;
            }
            const ull* aA = (const ull*)A + lane;
            const ull* aB = (const ull*)B + lane;
            #pragma unroll 4
            for (int k = 0; k < H1; k++) {
                ull a01 = aA[k * PTS];
                ull a23 = aB[k * PTS];
                const ulonglong2* wr = (const ulonglong2*)(W2dup + k * H2 + j0);
                #pragma unroll
                for (int g = 0; g < 4; g++) {
                    ulonglong2 wv = wr[g];
                    acc01[g * 2 + 0] = ffma2(a01, wv.x, acc01[g * 2 + 0]);
                    acc23[g * 2 + 0] = ffma2(a23, wv.x, acc23[g * 2 + 0]);
                    acc01[g * 2 + 1] = ffma2(a01, wv.y, acc01[g * 2 + 1]);
                    acc23[g * 2 + 1] = ffma2(a23, wv.y, acc23[g * 2 + 1]);
                }
            }
            ull h01[8], h23[8];
            #pragma unroll
            for (int c = 0; c < 8; c++)
                tanh_jvp(acc01[c], acc23[c], &h01[c], &h23[c]);
            __syncthreads();   // all reads of layer-1 activations done
            ull* oA = (ull*)A;
            ull* oB = (ull*)B;
            #pragma unroll
            for (int c = 0; c < 8; c++) {
                int j = j0 + c;
                oA[j * PTS + lane] = h01[c];
                oB[j * PTS + lane] = h23[c];
            }
        }
        __syncthreads();

        // ---------------- Layer 3: 128 -> 64 (in-place) ----------------
        // 16 warps x 4 cols; scalar W3 + 4 pack MOVs per k.
        {
            const int j0 = warp * 4;
            ull acc01[4], acc23[4];
            {
                float4 bb = __ldg(&((const float4*)b3)[j0 / 4]);
                acc01[0] = pack2(bb.x, 0.0f);
                acc01[1] = pack2(bb.y, 0.0f);
                acc01[2] = pack2(bb.z, 0.0f);
                acc01[3] = pack2(bb.w, 0.0f);
                acc23[0] = 0ULL; acc23[1] = 0ULL;
                acc23[2] = 0ULL; acc23[3] = 0ULL;
            }
            const ull* aA = (const ull*)A + lane;
            const ull* aB = (const ull*)B + lane;
            #pragma unroll 4
            for (int k = 0; k < H2; k++) {
                ull a01 = aA[k * PTS];
                ull a23 = aB[k * PTS];
                float4 w = *(const float4*)(W3s + k * H3 + j0);
                ull w0 = pack2(w.x, w.x), w1 = pack2(w.y, w.y);
                ull w2 = pack2(w.z, w.z), w3 = pack2(w.w, w.w);
                acc01[0] = ffma2(a01, w0, acc01[0]);
                acc23[0] = ffma2(a23, w0, acc23[0]);
                acc01[1] = ffma2(a01, w1, acc01[1]);
                acc23[1] = ffma2(a23, w1, acc23[1]);
                acc01[2] = ffma2(a01, w2, acc01[2]);
                acc23[2] = ffma2(a23, w2, acc23[2]);
                acc01[3] = ffma2(a01, w3, acc01[3]);
                acc23[3] = ffma2(a23, w3, acc23[3]);
            }
            ull h01[4], h23[4];
            #pragma unroll
            for (int c = 0; c < 4; c++)
                tanh_jvp(acc01[c], acc23[c], &h01[c], &h23[c]);
            __syncthreads();   // all reads of layer-2 activations done
            ull* oA = (ull*)A;
            ull* oB = (ull*)B;
            #pragma unroll
            for (int c = 0; c < 4; c++) {
                int j = j0 + c;
                oA[j * PTS + lane] = h01[c];
                oB[j * PTS + lane] = h23[c];
            }
        }
        __syncthreads();

        // ---------------- Layer 4: 64 -> 1 (4 dots per point) ------------
        if (tid < 128) {
            const int q = tid >> 5;            // quantity 0..3
            const int p = tid & 31;            // point
            const float2* hb = (q < 2 ? A : B);
            const bool hi = (q & 1);
            float dot = (q == 0) ? __ldg(&b4[0]) : 0.0f;
            #pragma unroll
            for (int k = 0; k < H3; k++) {
                float2 v = hb[k * PTS + p];
                dot = fmaf(hi ? v.y : v.x, __ldg(&W4[k]), dot);
            }
            out[(tile * PTS + p) * 4 + q] = dot;
        }
        __syncthreads();   // A/B reads done before next tile overwrites
    }
}

extern "C" void kernel_launch(void* const* d_in, const int* in_sizes, int n_in,
                              void* d_out, int out_size)
{
    const float* x  = (const float*)d_in[0];
    const float* W1 = (const float*)d_in[1];
    const float* b1 = (const float*)d_in[2];
    const float* W2 = (const float*)d_in[3];
    const float* b2 = (const float*)d_in[4];
    const float* W3 = (const float*)d_in[5];
    const float* b3 = (const float*)d_in[6];
    const float* W4 = (const float*)d_in[7];
    const float* b4 = (const float*)d_in[8];
    float* out = (float*)d_out;

    const int N = in_sizes[0] / 3;   // 262144
    const int n_tiles = N / PTS;     // 8192
    // A(32KB)+B(32KB)+W2dup(128KB)+W3s(32KB) = 224KB
    const int smem_bytes = (2 * H1 * PTS * 2 + H1 * H2 * 2 + H2 * H3)
                           * (int)sizeof(float);

    cudaFuncSetAttribute(pinn_fused_kernel,
                         cudaFuncAttributeMaxDynamicSharedMemorySize, smem_bytes);

    pinn_fused_kernel<<<NSM, TPB, smem_bytes>>>(
        x, W1, b1, W2, b2, W3, b3, W4, b4, out, n_tiles);
}